// round 1
// baseline (speedup 1.0000x reference)
#include <cuda_runtime.h>
#include <math.h>

// Problem constants
#define DIMV    16
#define ROWS    64        // 2*HEADS*DIM
#define EMB     64
#define RH      2
#define OUTN    1024      // ROWS*COLS
#define UNITS   1184      // OUT + 2*ROWS + 2*COLS
#define ZDIM    4736      // 4*UNITS
#define BQ      128       // B*Q = 8*16
#define LNUM    65        // ROWS+1 sequence positions

// Precomputed constants (device globals; no allocation allowed)
__device__ float g_KC[64 * 2 * 64];   // [l-1][h][k] for l = 1..64
__device__ float g_VC[64 * 2 * 64];
__device__ float g_oT[64 * 128];      // o transposed: [d][b]

__device__ __forceinline__ float sigf(float x) { return 1.0f / (1.0f + expf(-x)); }

// Decay sum for one channel: pc = this channel, po = other channel.
// pre = [0, pc, po, inf]; STD=[100,100,100,1]; MEAN=[0.5,0.07879465,0.06618887,0];
// COND=[0.07915332,1.0334609,1.3365093,0.4505964]; TGT=[1.5931877,1.4378392,0,0].
__device__ __forceinline__ float decay_sum(float pc, float po) {
    float t0 = 0.07915332f * sigf(100.0f * (0.0f - 0.5f)) * (1.5931877f - pc);
    float t1 = 1.0334609f  * sigf(100.0f * (pc - 0.07879465f)) * (1.4378392f - pc);
    float t2 = 1.3365093f  * sigf(100.0f * (po - 0.06618887f)) * (0.0f - pc);
    float t3 = 0.4505964f  * 1.0f /* sigmoid(+inf) */ * (0.0f - pc);
    return t0 + t1 + t2 + t3;
}

// pot scalar after 7 scan steps (output at step 7 uses carry after 7 decays),
// each decay = DSTEPS=2 inner updates. pot0 = (0, 1). Returns channel 0.
__device__ __forceinline__ float pot_scalar() {
    float p0 = 0.0f, p1 = 1.0f;
    const float PART = (float)(1.5573331 / 2.0);
    for (int s = 0; s < 7; s++) {
        for (int d = 0; d < 2; d++) {
            float n0 = decay_sum(p0, p1);
            float n1 = decay_sum(p1, p0);
            p0 += n0 * PART;
            p1 += n1 * PART;
        }
    }
    return p0;
}

// Positional encoding PE[l][i], matching numpy float64 math then cast to f32.
__device__ __forceinline__ float pe_val(int l, int i) {
    double e = (double)(2 * (i / 2)) / 64.0;
    double ang = (double)l / pow(10000.0, e);
    return (float)((i % 2 == 0) ? sin(ang) : cos(ang));
}

// ---------------------------------------------------------------------------
// Kernel 1: constant K/V rows for l = 1..64.
// grid = 64 (one block per l), block = 128.
// ---------------------------------------------------------------------------
__global__ void k_precompute(const float* __restrict__ Wm, const float* __restrict__ bm,
                             const float* __restrict__ Wk, const float* __restrict__ bk,
                             const float* __restrict__ Wv, const float* __restrict__ bv) {
    int l = blockIdx.x + 1;           // 1..64
    int t = threadIdx.x;
    __shared__ float aug[64];

    if (t < 64) {
        float m = pot_scalar();
        float s = 0.0f;
        for (int i = 0; i < 256; i++) s += Wm[i * 64 + t];   // column sum of Wm
        aug[t] = m * s + bm[t] + pe_val(l, t);
    }
    __syncthreads();

    // t = h*64 + kk
    float ak = bk[t], av = bv[t];
    for (int d = 0; d < 64; d++) {
        float a = aug[d];
        ak += a * Wk[d * 128 + t];
        av += a * Wv[d * 128 + t];
    }
    g_KC[(l - 1) * 128 + t] = ak;
    g_VC[(l - 1) * 128 + t] = av;
}

// ---------------------------------------------------------------------------
// Kernel 2: per-batch-row attention -> o vector.
// grid = 128 (one block per b), block = 128.
// ---------------------------------------------------------------------------
__global__ void k_attn(const float* __restrict__ queries, const float* __restrict__ values,
                       const float* __restrict__ Wi, const float* __restrict__ bi,
                       const float* __restrict__ Wq, const float* __restrict__ bq,
                       const float* __restrict__ Wk, const float* __restrict__ bk,
                       const float* __restrict__ Wv, const float* __restrict__ bv,
                       const float* __restrict__ Wo, const float* __restrict__ bo) {
    int b = blockIdx.x;
    int t = threadIdx.x;

    __shared__ float x[32];
    __shared__ float aug0[64];
    __shared__ float q[128], k0[128], v0[128];
    __shared__ float logit[130];   // [h][l], h-major
    __shared__ float attn[130];
    __shared__ float ctx[128];

    // x = concat(queries[b], values[b/16, 7, :])
    if (t < 16)       x[t] = queries[b * 16 + t];
    else if (t < 32)  x[t] = values[(b / 16) * 128 + 112 + (t - 16)];
    __syncthreads();

    // emb_in + PE[0]  (PE[0][j] = 0 for even j, 1 for odd j)
    if (t < 64) {
        float s = bi[t];
        #pragma unroll
        for (int i = 0; i < 32; i++) s += x[i] * Wi[i * 64 + t];
        aug0[t] = s + ((t & 1) ? 1.0f : 0.0f);
    }
    __syncthreads();

    // q, k0, v0  (t = h*64 + kk)
    {
        float aq = bq[t], ak = bk[t], av = bv[t];
        for (int d = 0; d < 64; d++) {
            float a = aug0[d];
            aq += a * Wq[d * 128 + t];
            ak += a * Wk[d * 128 + t];
            av += a * Wv[d * 128 + t];
        }
        q[t] = aq; k0[t] = ak; v0[t] = av;
    }
    __syncthreads();

    // logits: 2 heads x 65 positions
    for (int i = t; i < 130; i += 128) {
        int h = i / 65, l = i % 65;
        const float* kp = (l == 0) ? &k0[h * 64] : &g_KC[(l - 1) * 128 + h * 64];
        float s = 0.0f;
        #pragma unroll
        for (int d = 0; d < 64; d++) s += q[h * 64 + d] * kp[d];
        logit[h * 65 + l] = s * 0.125f;   // 1/sqrt(64)
    }
    __syncthreads();

    // softmax per head (serial by 2 threads; 65 elements each)
    if (t < 2) {
        int base = t * 65;
        float mx = -1e30f;
        for (int l = 0; l < 65; l++) mx = fmaxf(mx, logit[base + l]);
        float sum = 0.0f;
        for (int l = 0; l < 65; l++) { float e = expf(logit[base + l] - mx); attn[base + l] = e; sum += e; }
        float inv = 1.0f / sum;
        for (int l = 0; l < 65; l++) attn[base + l] *= inv;
    }
    __syncthreads();

    // ctx[h][kk] = sum_l attn[h][l] * v_l[h][kk]
    {
        int h = t >> 6;
        float s = attn[h * 65] * v0[t];
        for (int l = 1; l < 65; l++) s += attn[h * 65 + l] * g_VC[(l - 1) * 128 + t];
        ctx[t] = s;
    }
    __syncthreads();

    // o[d] = sum_{h,k} ctx[h,k] * Wo[h,k,d] + bo[d]; store transposed
    if (t < 64) {
        float s = bo[t];
        for (int hk = 0; hk < 128; hk++) s += ctx[hk] * Wo[hk * 64 + t];
        g_oT[t * 128 + b] = s;
    }
}

// ---------------------------------------------------------------------------
// Kernel 3: z = o @ Wx (only zi/zg/zo column groups) + gating -> output.
// grid = 128 (8 output columns each), block = 128 (thread = b).
// ---------------------------------------------------------------------------
__global__ void k_gemm_gate(const float* __restrict__ Wx, const float* __restrict__ bl,
                            float* __restrict__ out) {
    int t = threadIdx.x;              // b
    int j0 = blockIdx.x * 8;          // 8 of the 1024 output columns

    float o[64];
    #pragma unroll
    for (int k = 0; k < 64; k++) o[k] = g_oT[k * 128 + t];   // coalesced

    __shared__ float W[8][3][64];     // [jj][grp][k]
    __shared__ float Bv[8][3];
    const int grpoff0 = 0, grpoff1 = 2368, grpoff2 = 3552;   // zi, zg, zo

    for (int idx = t; idx < 8 * 3 * 64; idx += 128) {
        int jj = idx & 7;
        int kg = idx >> 3;
        int g  = kg % 3;
        int k  = kg / 3;
        int go = (g == 0) ? grpoff0 : (g == 1) ? grpoff1 : grpoff2;
        W[jj][g][k] = Wx[k * ZDIM + go + j0 + jj];
    }
    if (t < 24) {
        int jj = t & 7, g = t >> 3;
        int go = (g == 0) ? grpoff0 : (g == 1) ? grpoff1 : grpoff2;
        Bv[jj][g] = bl[go + j0 + jj];
    }
    __syncthreads();

    for (int jj = 0; jj < 8; jj++) {
        float zi = Bv[jj][0], zg = Bv[jj][1], zo = Bv[jj][2];
        #pragma unroll
        for (int k = 0; k < 64; k++) {
            float ok = o[k];
            zi += ok * W[jj][0][k];
            zg += ok * W[jj][1][k];
            zo += ok * W[jj][2][k];
        }
        float c = sigf(zi) * tanhf(zg);
        float h = sigf(zo) * tanhf(c);
        out[t * 1024 + j0 + jj] = h;
    }
}

// ---------------------------------------------------------------------------
extern "C" void kernel_launch(void* const* d_in, const int* in_sizes, int n_in,
                              void* d_out, int out_size) {
    const float* queries = (const float*)d_in[0];
    const float* values  = (const float*)d_in[1];
    const float* Wi      = (const float*)d_in[2];
    const float* bi      = (const float*)d_in[3];
    const float* Wm      = (const float*)d_in[4];
    const float* bm      = (const float*)d_in[5];
    const float* Wq      = (const float*)d_in[6];
    const float* bq      = (const float*)d_in[7];
    const float* Wk      = (const float*)d_in[8];
    const float* bk      = (const float*)d_in[9];
    const float* Wv      = (const float*)d_in[10];
    const float* bv      = (const float*)d_in[11];
    const float* Wo      = (const float*)d_in[12];
    const float* bo      = (const float*)d_in[13];
    const float* Wx      = (const float*)d_in[14];
    const float* bl      = (const float*)d_in[15];
    float* out = (float*)d_out;

    k_precompute<<<64, 128>>>(Wm, bm, Wk, bk, Wv, bv);
    k_attn<<<128, 128>>>(queries, values, Wi, bi, Wq, bq, Wk, bk, Wv, bv, Wo, bo);
    k_gemm_gate<<<128, 128>>>(Wx, bl, out);
}

// round 3
// speedup vs baseline: 1.1484x; 1.1484x over previous
#include <cuda_runtime.h>
#include <math.h>

#define ZDIM    4736      // 4*UNITS
#define LN10K   9.210340371976184f   // ln(10000)

// Precomputed constants (device globals; no allocation allowed)
__device__ float g_KC[64 * 2 * 64];   // [l-1][h][k] for l = 1..64
__device__ float g_VC[64 * 2 * 64];
__device__ float g_oT[64 * 128];      // o transposed: [d][b]

__device__ __forceinline__ float sigd(float x) { return 1.0f / (1.0f + __expf(-x)); }

// Positional encoding PE[l][i] in fp32 (ref uses f64 then casts; diff ~1e-6 << 1e-3 tol)
__device__ __forceinline__ float pe_val(int l, int i) {
    float e = (float)(2 * (i / 2)) * (1.0f / 64.0f);
    float invfreq = __expf(-e * LN10K);
    float ang = (float)l * invfreq;
    return (i & 1) ? cosf(ang) : sinf(ang);
}

// ---------------------------------------------------------------------------
// Kernel 1: constant K/V rows for l = 1..64.  m passed from host.
// grid = 64 (one block per l), block = 128.
// ---------------------------------------------------------------------------
__global__ void k_precompute(const float* __restrict__ Wm, const float* __restrict__ bm,
                             const float* __restrict__ Wk, const float* __restrict__ bk,
                             const float* __restrict__ Wv, const float* __restrict__ bv,
                             float m) {
    int l = blockIdx.x + 1;           // 1..64
    int t = threadIdx.x;
    __shared__ float part[128];
    __shared__ float aug[64];

    // Column sum of Wm, split across two thread halves per column
    {
        int col = t & 63, half = t >> 6;
        float s = 0.0f;
        #pragma unroll 4
        for (int i = half * 128; i < half * 128 + 128; i++) s += Wm[i * 64 + col];
        part[t] = s;
    }
    __syncthreads();
    if (t < 64) aug[t] = m * (part[t] + part[t + 64]) + bm[t] + pe_val(l, t);
    __syncthreads();

    // t = h*64 + kk
    float ak = bk[t], av = bv[t];
    #pragma unroll 8
    for (int d = 0; d < 64; d++) {
        float a = aug[d];
        ak += a * Wk[d * 128 + t];
        av += a * Wv[d * 128 + t];
    }
    g_KC[(l - 1) * 128 + t] = ak;
    g_VC[(l - 1) * 128 + t] = av;
}

// ---------------------------------------------------------------------------
// Kernel 2: per-batch-row attention -> o vector.
// grid = 128 (one block per b), block = 128.
// ---------------------------------------------------------------------------
__global__ void k_attn(const float* __restrict__ queries, const float* __restrict__ values,
                       const float* __restrict__ Wi, const float* __restrict__ bi,
                       const float* __restrict__ Wq, const float* __restrict__ bq,
                       const float* __restrict__ Wk, const float* __restrict__ bk,
                       const float* __restrict__ Wv, const float* __restrict__ bv,
                       const float* __restrict__ Wo, const float* __restrict__ bo) {
    int b = blockIdx.x;
    int t = threadIdx.x;

    __shared__ float x[32];
    __shared__ float aug0[64];
    __shared__ float q[128], k0[128], v0[128];
    __shared__ float logit[130];   // [h][l], h-major
    __shared__ float attn[130];
    __shared__ float ctx[128];
    __shared__ float opart[128];

    // x = concat(queries[b], values[b/16, 7, :])
    if (t < 16)       x[t] = queries[b * 16 + t];
    else if (t < 32)  x[t] = values[(b / 16) * 128 + 112 + (t - 16)];
    __syncthreads();

    // emb_in + PE[0]  (PE[0][j] = 0 for even j, 1 for odd j)
    if (t < 64) {
        float s = bi[t];
        #pragma unroll
        for (int i = 0; i < 32; i++) s += x[i] * Wi[i * 64 + t];
        aug0[t] = s + ((t & 1) ? 1.0f : 0.0f);
    }
    __syncthreads();

    // q, k0, v0  (t = h*64 + kk)
    {
        float aq = bq[t], ak = bk[t], av = bv[t];
        #pragma unroll 8
        for (int d = 0; d < 64; d++) {
            float a = aug0[d];
            aq += a * Wq[d * 128 + t];
            ak += a * Wk[d * 128 + t];
            av += a * Wv[d * 128 + t];
        }
        q[t] = aq; k0[t] = ak; v0[t] = av;
    }
    __syncthreads();

    // logits: 2 heads x 65 positions
    for (int i = t; i < 130; i += 128) {
        int h = i / 65, l = i % 65;
        const float* kp = (l == 0) ? &k0[h * 64] : &g_KC[(l - 1) * 128 + h * 64];
        float s = 0.0f;
        #pragma unroll
        for (int d = 0; d < 64; d++) s += q[h * 64 + d] * kp[d];
        logit[h * 65 + l] = s * 0.125f;   // 1/sqrt(64)
    }
    __syncthreads();

    // softmax per head: warp 0 -> head 0, warp 1 -> head 1
    {
        int w = t >> 5, lane = t & 31;
        if (w < 2) {
            int base = w * 65;
            float a0 = logit[base + lane];
            float a1 = logit[base + 32 + lane];
            float a2 = (lane == 0) ? logit[base + 64] : -1e30f;
            float mx = fmaxf(fmaxf(a0, a1), a2);
            #pragma unroll
            for (int off = 16; off > 0; off >>= 1)
                mx = fmaxf(mx, __shfl_xor_sync(0xffffffffu, mx, off));
            float e0 = __expf(a0 - mx);
            float e1 = __expf(a1 - mx);
            float e2 = (lane == 0) ? __expf(a2 - mx) : 0.0f;
            float sum = e0 + e1 + e2;
            #pragma unroll
            for (int off = 16; off > 0; off >>= 1)
                sum += __shfl_xor_sync(0xffffffffu, sum, off);
            float inv = 1.0f / sum;
            attn[base + lane] = e0 * inv;
            attn[base + 32 + lane] = e1 * inv;
            if (lane == 0) attn[base + 64] = e2 * inv;
        }
    }
    __syncthreads();

    // ctx[h][kk] = sum_l attn[h][l] * v_l[h][kk]
    {
        int h = t >> 6;
        float s = attn[h * 65] * v0[t];
        #pragma unroll 8
        for (int l = 1; l < 65; l++) s += attn[h * 65 + l] * g_VC[(l - 1) * 128 + t];
        ctx[t] = s;
    }
    __syncthreads();

    // o[d] = sum_{h,k} ctx[h,k] * Wo[h,k,d] + bo[d]; split across halves, store transposed
    {
        int col = t & 63, half = t >> 6;
        float s = half ? 0.0f : bo[col];
        #pragma unroll 8
        for (int hk = half * 64; hk < half * 64 + 64; hk++)
            s += ctx[hk] * Wo[hk * 64 + col];
        opart[t] = s;
    }
    __syncthreads();
    if (t < 64) g_oT[t * 128 + b] = opart[t] + opart[t + 64];
}

// ---------------------------------------------------------------------------
// Kernel 3: z = o @ Wx (only zi/zg/zo column groups) + gating -> output.
// grid = 128 (8 output columns each), block = 128 (thread = b).
// ---------------------------------------------------------------------------
__global__ void k_gemm_gate(const float* __restrict__ Wx, const float* __restrict__ bl,
                            float* __restrict__ out) {
    int t = threadIdx.x;              // b
    int j0 = blockIdx.x * 8;          // 8 of the 1024 output columns

    float o[64];
    #pragma unroll
    for (int k = 0; k < 64; k++) o[k] = g_oT[k * 128 + t];   // coalesced

    __shared__ float W[8][3][64];     // [jj][grp][k]
    __shared__ float Bv[8][3];
    __shared__ float Hs[8][132];      // padded to dodge bank conflicts
    const int grpoff0 = 0, grpoff1 = 2368, grpoff2 = 3552;   // zi, zg, zo

    for (int idx = t; idx < 8 * 3 * 64; idx += 128) {
        int jj = idx & 7;
        int kg = idx >> 3;
        int g  = kg % 3;
        int k  = kg / 3;
        int go = (g == 0) ? grpoff0 : (g == 1) ? grpoff1 : grpoff2;
        W[jj][g][k] = Wx[k * ZDIM + go + j0 + jj];
    }
    if (t < 24) {
        int jj = t & 7, g = t >> 3;
        int go = (g == 0) ? grpoff0 : (g == 1) ? grpoff1 : grpoff2;
        Bv[jj][g] = bl[go + j0 + jj];
    }
    __syncthreads();

    #pragma unroll
    for (int jj = 0; jj < 8; jj++) {
        float zi = Bv[jj][0], zg = Bv[jj][1], zo = Bv[jj][2];
        #pragma unroll
        for (int k = 0; k < 64; k++) {
            float ok = o[k];
            zi += ok * W[jj][0][k];
            zg += ok * W[jj][1][k];
            zo += ok * W[jj][2][k];
        }
        float c = sigd(zi) * tanhf(zg);
        Hs[jj][t] = sigd(zo) * tanhf(c);
    }
    __syncthreads();

    // staged writes: 8 consecutive floats per b, ordered for coalescing
    for (int idx = t; idx < 1024; idx += 128) {
        int jj = idx & 7, b = idx >> 3;
        out[b * 1024 + j0 + jj] = Hs[jj][b];
    }
}

// ---------------------------------------------------------------------------
// Host-side replica of the pot decay (input-independent -> compute once here).
static float sig_h(float x) { return 1.0f / (1.0f + expf(-x)); }
static float decay_h(float pc, float po) {
    float t0 = 0.07915332f * sig_h(100.0f * (0.0f - 0.5f)) * (1.5931877f - pc);
    float t1 = 1.0334609f  * sig_h(100.0f * (pc - 0.07879465f)) * (1.4378392f - pc);
    float t2 = 1.3365093f  * sig_h(100.0f * (po - 0.06618887f)) * (0.0f - pc);
    float t3 = 0.4505964f  * (0.0f - pc);
    return t0 + t1 + t2 + t3;
}
static float pot_scalar_h() {
    float p0 = 0.0f, p1 = 1.0f;
    const float PART = (float)(1.5573331 / 2.0);
    for (int s = 0; s < 7; s++)
        for (int d = 0; d < 2; d++) {
            float n0 = decay_h(p0, p1);
            float n1 = decay_h(p1, p0);
            p0 += n0 * PART;
            p1 += n1 * PART;
        }
    return p0;
}

extern "C" void kernel_launch(void* const* d_in, const int* in_sizes, int n_in,
                              void* d_out, int out_size) {
    const float* queries = (const float*)d_in[0];
    const float* values  = (const float*)d_in[1];
    const float* Wi      = (const float*)d_in[2];
    const float* bi      = (const float*)d_in[3];
    const float* Wm      = (const float*)d_in[4];
    const float* bm      = (const float*)d_in[5];
    const float* Wq      = (const float*)d_in[6];
    const float* bq      = (const float*)d_in[7];
    const float* Wk      = (const float*)d_in[8];
    const float* bk      = (const float*)d_in[9];
    const float* Wv      = (const float*)d_in[10];
    const float* bv      = (const float*)d_in[11];
    const float* Wo      = (const float*)d_in[12];
    const float* bo      = (const float*)d_in[13];
    const float* Wx      = (const float*)d_in[14];
    const float* bl      = (const float*)d_in[15];
    float* out = (float*)d_out;

    float m = pot_scalar_h();

    k_precompute<<<64, 128>>>(Wm, bm, Wk, bk, Wv, bv, m);
    k_attn<<<128, 128>>>(queries, values, Wi, bi, Wq, bq, Wk, bk, Wv, bv, Wo, bo);
    k_gemm_gate<<<128, 128>>>(Wx, bl, out);
}

// round 4
// speedup vs baseline: 1.6674x; 1.4520x over previous
#include <cuda_runtime.h>
#include <math.h>

#define ZDIM    4736      // 4*UNITS
#define LN10K   9.210340371976184f   // ln(10000)

// Precomputed constants (device globals; no allocation allowed)
__device__ float g_KC[64 * 2 * 64];   // [l-1][h][k] for l = 1..64
__device__ float g_VC[64 * 2 * 64];
__device__ float g_oT[64 * 128];      // o transposed: [d][b]

__device__ __forceinline__ float sigd(float x) { return 1.0f / (1.0f + __expf(-x)); }

// Positional encoding PE[l][i] in fp32 (ref uses f64 then casts; diff ~1e-6 << 1e-3 tol)
__device__ __forceinline__ float pe_val(int l, int i) {
    float e = (float)(2 * (i / 2)) * (1.0f / 64.0f);
    float invfreq = __expf(-e * LN10K);
    float ang = (float)l * invfreq;
    return (i & 1) ? cosf(ang) : sinf(ang);
}

// ---------------------------------------------------------------------------
// Kernel 1: constant K/V rows for l = 1..64.  m passed from host.
// grid = 64 (one block per l), block = 256.
//   Phase 1: colsum(Wm) with 4-way row split + 8 independent accumulators (high MLP)
//   Phase 2: aug vector
//   Phase 3: threads 0-127 -> K row, threads 128-255 -> V row (fully unrolled)
// ---------------------------------------------------------------------------
__global__ void __launch_bounds__(256) k_precompute(
        const float* __restrict__ Wm, const float* __restrict__ bm,
        const float* __restrict__ Wk, const float* __restrict__ bk,
        const float* __restrict__ Wv, const float* __restrict__ bv,
        float m) {
    int l = blockIdx.x + 1;           // 1..64
    int t = threadIdx.x;
    __shared__ float part[256];
    __shared__ float aug[64];

    // Phase 1: column sum of Wm[256][64]; quarter q sums rows q*64..q*64+63
    {
        int col = t & 63, q = t >> 6;
        const float* base = Wm + (q * 64) * 64 + col;
        float a0 = 0.f, a1 = 0.f, a2 = 0.f, a3 = 0.f, a4 = 0.f, a5 = 0.f, a6 = 0.f, a7 = 0.f;
        #pragma unroll
        for (int i = 0; i < 64; i += 8) {
            a0 += base[(i + 0) * 64];
            a1 += base[(i + 1) * 64];
            a2 += base[(i + 2) * 64];
            a3 += base[(i + 3) * 64];
            a4 += base[(i + 4) * 64];
            a5 += base[(i + 5) * 64];
            a6 += base[(i + 6) * 64];
            a7 += base[(i + 7) * 64];
        }
        part[t] = ((a0 + a1) + (a2 + a3)) + ((a4 + a5) + (a6 + a7));
    }
    __syncthreads();
    if (t < 64) {
        float cs = part[t] + part[t + 64] + part[t + 128] + part[t + 192];
        aug[t] = m * cs + bm[t] + pe_val(l, t);
    }
    __syncthreads();

    // Phase 3: split K / V across thread halves; full unroll -> batched loads
    {
        int tt = t & 127, half = t >> 7;
        const float* W  = half ? Wv : Wk;
        const float* bb = half ? bv : bk;
        float* dst      = half ? g_VC : g_KC;
        float a = bb[tt];
        #pragma unroll
        for (int d = 0; d < 64; d++) a += aug[d] * W[d * 128 + tt];
        dst[(l - 1) * 128 + tt] = a;
    }
}

// ---------------------------------------------------------------------------
// Kernel 2: per-batch-row attention -> o vector.
// grid = 128 (one block per b), block = 128.
// ---------------------------------------------------------------------------
__global__ void __launch_bounds__(128) k_attn(
        const float* __restrict__ queries, const float* __restrict__ values,
        const float* __restrict__ Wi, const float* __restrict__ bi,
        const float* __restrict__ Wq, const float* __restrict__ bq,
        const float* __restrict__ Wk, const float* __restrict__ bk,
        const float* __restrict__ Wv, const float* __restrict__ bv,
        const float* __restrict__ Wo, const float* __restrict__ bo) {
    int b = blockIdx.x;
    int t = threadIdx.x;

    __shared__ float x[32];
    __shared__ float aug0[64];
    __shared__ float q[128], k0[128], v0[128];
    __shared__ float logit[130];   // [h][l], h-major
    __shared__ float attn[130];
    __shared__ float ctx[128];
    __shared__ float opart[128];

    // x = concat(queries[b], values[b/16, 7, :])
    if (t < 16)       x[t] = queries[b * 16 + t];
    else if (t < 32)  x[t] = values[(b / 16) * 128 + 112 + (t - 16)];
    __syncthreads();

    // emb_in + PE[0]  (PE[0][j] = 0 for even j, 1 for odd j)
    if (t < 64) {
        float s = bi[t];
        #pragma unroll
        for (int i = 0; i < 32; i++) s += x[i] * Wi[i * 64 + t];
        aug0[t] = s + ((t & 1) ? 1.0f : 0.0f);
    }
    __syncthreads();

    // q, k0, v0  (t = h*64 + kk); full unroll for load batching
    {
        float aq = bq[t], ak = bk[t], av = bv[t];
        #pragma unroll
        for (int d = 0; d < 64; d++) {
            float a = aug0[d];
            aq += a * Wq[d * 128 + t];
            ak += a * Wk[d * 128 + t];
            av += a * Wv[d * 128 + t];
        }
        q[t] = aq; k0[t] = ak; v0[t] = av;
    }
    __syncthreads();

    // logits: 2 heads x 65 positions
    for (int i = t; i < 130; i += 128) {
        int h = i / 65, l = i % 65;
        const float* kp = (l == 0) ? &k0[h * 64] : &g_KC[(l - 1) * 128 + h * 64];
        float s = 0.0f;
        #pragma unroll
        for (int d = 0; d < 64; d++) s += q[h * 64 + d] * kp[d];
        logit[h * 65 + l] = s * 0.125f;   // 1/sqrt(64)
    }
    __syncthreads();

    // softmax per head: warp 0 -> head 0, warp 1 -> head 1
    {
        int w = t >> 5, lane = t & 31;
        if (w < 2) {
            int base = w * 65;
            float a0 = logit[base + lane];
            float a1 = logit[base + 32 + lane];
            float a2 = (lane == 0) ? logit[base + 64] : -1e30f;
            float mx = fmaxf(fmaxf(a0, a1), a2);
            #pragma unroll
            for (int off = 16; off > 0; off >>= 1)
                mx = fmaxf(mx, __shfl_xor_sync(0xffffffffu, mx, off));
            float e0 = __expf(a0 - mx);
            float e1 = __expf(a1 - mx);
            float e2 = (lane == 0) ? __expf(a2 - mx) : 0.0f;
            float sum = e0 + e1 + e2;
            #pragma unroll
            for (int off = 16; off > 0; off >>= 1)
                sum += __shfl_xor_sync(0xffffffffu, sum, off);
            float inv = 1.0f / sum;
            attn[base + lane] = e0 * inv;
            attn[base + 32 + lane] = e1 * inv;
            if (lane == 0) attn[base + 64] = e2 * inv;
        }
    }
    __syncthreads();

    // ctx[h][kk] = sum_l attn[h][l] * v_l[h][kk]; full unroll for load batching
    {
        int h = t >> 6;
        float s = attn[h * 65] * v0[t];
        #pragma unroll
        for (int l = 1; l < 65; l++) s += attn[h * 65 + l] * g_VC[(l - 1) * 128 + t];
        ctx[t] = s;
    }
    __syncthreads();

    // o[d] = sum_{h,k} ctx[h,k] * Wo[h,k,d] + bo[d]; split across halves
    {
        int col = t & 63, half = t >> 6;
        float s = half ? 0.0f : bo[col];
        const float* Wp = Wo + (half * 64) * 64 + col;
        #pragma unroll
        for (int hk = 0; hk < 64; hk++)
            s += ctx[half * 64 + hk] * Wp[hk * 64];
        opart[t] = s;
    }
    __syncthreads();
    if (t < 64) g_oT[t * 128 + b] = opart[t] + opart[t + 64];
}

// ---------------------------------------------------------------------------
// Kernel 3: z = o @ Wx (only zi/zg/zo column groups) + gating -> output.
// grid = 128 (8 output columns each), block = 128 (thread = b).
// Inner product reads W via broadcast float4 LDS (4x fewer shared reads).
// ---------------------------------------------------------------------------
__global__ void __launch_bounds__(128) k_gemm_gate(
        const float* __restrict__ Wx, const float* __restrict__ bl,
        float* __restrict__ out) {
    int t = threadIdx.x;              // b
    int j0 = blockIdx.x * 8;          // 8 of the 1024 output columns

    float o[64];
    #pragma unroll
    for (int k = 0; k < 64; k++) o[k] = g_oT[k * 128 + t];   // coalesced

    __shared__ __align__(16) float W[8][3][64];   // [jj][grp][k]
    __shared__ float Bv[8][3];
    __shared__ float Hs[8][132];      // padded to dodge bank conflicts
    const int grpoff0 = 0, grpoff1 = 2368, grpoff2 = 3552;   // zi, zg, zo

    #pragma unroll
    for (int r = 0; r < 12; r++) {
        int idx = r * 128 + t;
        int jj = idx & 7;
        int kg = idx >> 3;
        int g  = kg % 3;
        int k  = kg / 3;
        int go = (g == 0) ? grpoff0 : (g == 1) ? grpoff1 : grpoff2;
        W[jj][g][k] = Wx[k * ZDIM + go + j0 + jj];
    }
    if (t < 24) {
        int jj = t & 7, g = t >> 3;
        int go = (g == 0) ? grpoff0 : (g == 1) ? grpoff1 : grpoff2;
        Bv[jj][g] = bl[go + j0 + jj];
    }
    __syncthreads();

    #pragma unroll
    for (int jj = 0; jj < 8; jj++) {
        float zi = Bv[jj][0], zg = Bv[jj][1], zo = Bv[jj][2];
        const float4* wi4 = (const float4*)W[jj][0];
        const float4* wg4 = (const float4*)W[jj][1];
        const float4* wo4 = (const float4*)W[jj][2];
        #pragma unroll
        for (int k4 = 0; k4 < 16; k4++) {
            float4 wi = wi4[k4], wg = wg4[k4], wo = wo4[k4];
            float o0 = o[4 * k4], o1 = o[4 * k4 + 1], o2 = o[4 * k4 + 2], o3 = o[4 * k4 + 3];
            zi += o0 * wi.x + o1 * wi.y + o2 * wi.z + o3 * wi.w;
            zg += o0 * wg.x + o1 * wg.y + o2 * wg.z + o3 * wg.w;
            zo += o0 * wo.x + o1 * wo.y + o2 * wo.z + o3 * wo.w;
        }
        float c = sigd(zi) * tanhf(zg);
        Hs[jj][t] = sigd(zo) * tanhf(c);
    }
    __syncthreads();

    // staged writes: 8 consecutive floats per b, ordered for coalescing
    #pragma unroll
    for (int r = 0; r < 8; r++) {
        int idx = r * 128 + t;
        int jj = idx & 7, b = idx >> 3;
        out[b * 1024 + j0 + jj] = Hs[jj][b];
    }
}

// ---------------------------------------------------------------------------
// Host-side replica of the pot decay (input-independent -> compute once here).
static float sig_h(float x) { return 1.0f / (1.0f + expf(-x)); }
static float decay_h(float pc, float po) {
    float t0 = 0.07915332f * sig_h(100.0f * (0.0f - 0.5f)) * (1.5931877f - pc);
    float t1 = 1.0334609f  * sig_h(100.0f * (pc - 0.07879465f)) * (1.4378392f - pc);
    float t2 = 1.3365093f  * sig_h(100.0f * (po - 0.06618887f)) * (0.0f - pc);
    float t3 = 0.4505964f  * (0.0f - pc);
    return t0 + t1 + t2 + t3;
}
static float pot_scalar_h() {
    float p0 = 0.0f, p1 = 1.0f;
    const float PART = (float)(1.5573331 / 2.0);
    for (int s = 0; s < 7; s++)
        for (int d = 0; d < 2; d++) {
            float n0 = decay_h(p0, p1);
            float n1 = decay_h(p1, p0);
            p0 += n0 * PART;
            p1 += n1 * PART;
        }
    return p0;
}

extern "C" void kernel_launch(void* const* d_in, const int* in_sizes, int n_in,
                              void* d_out, int out_size) {
    const float* queries = (const float*)d_in[0];
    const float* values  = (const float*)d_in[1];
    const float* Wi      = (const float*)d_in[2];
    const float* bi      = (const float*)d_in[3];
    const float* Wm      = (const float*)d_in[4];
    const float* bm      = (const float*)d_in[5];
    const float* Wq      = (const float*)d_in[6];
    const float* bq      = (const float*)d_in[7];
    const float* Wk      = (const float*)d_in[8];
    const float* bk      = (const float*)d_in[9];
    const float* Wv      = (const float*)d_in[10];
    const float* bv      = (const float*)d_in[11];
    const float* Wo      = (const float*)d_in[12];
    const float* bo      = (const float*)d_in[13];
    const float* Wx      = (const float*)d_in[14];
    const float* bl      = (const float*)d_in[15];
    float* out = (float*)d_out;

    float m = pot_scalar_h();

    k_precompute<<<64, 256>>>(Wm, bm, Wk, bk, Wv, bv, m);
    k_attn<<<128, 128>>>(queries, values, Wi, bi, Wq, bq, Wk, bk, Wv, bv, Wo, bo);
    k_gemm_gate<<<128, 128>>>(Wx, bl, out);
}

// round 5
// speedup vs baseline: 1.9587x; 1.1747x over previous
#include <cuda_runtime.h>
#include <math.h>

#define ZDIM    4736      // 4*UNITS
#define LN10K   9.210340371976184f
#define NBLK    128
#define NTHR    256

// Device globals (no allocation allowed)
__device__ float g_KC[64 * 2 * 64];   // [l-1][h][k] for l = 1..64
__device__ float g_VC[64 * 2 * 64];
__device__ float g_oT[64 * 128];      // o transposed: [d][b]
__device__ unsigned g_bar1 = 0, g_bar2 = 0, g_done = 0;

__device__ __forceinline__ float sigd(float x) { return 1.0f / (1.0f + __expf(-x)); }

__device__ __forceinline__ float pe_val(int l, int i) {
    float e = (float)(2 * (i / 2)) * (1.0f / 64.0f);
    float invfreq = __expf(-e * LN10K);
    float ang = (float)l * invfreq;
    return (i & 1) ? cosf(ang) : sinf(ang);
}

// Grid-wide barrier: all 128 blocks are co-resident (<=148 SMs), so spinning is safe.
__device__ __forceinline__ void grid_bar(unsigned* ctr) {
    __syncthreads();
    if (threadIdx.x == 0) {
        __threadfence();
        atomicAdd(ctr, 1u);
        volatile unsigned* v = (volatile unsigned*)ctr;
        while (*v < (unsigned)NBLK) __nanosleep(32);
        __threadfence();
    }
    __syncthreads();
}

// ---------------------------------------------------------------------------
// Single fused kernel. grid = 128 (block b = batch row), block = 256.
// ---------------------------------------------------------------------------
__global__ void __launch_bounds__(NTHR) k_fused(
        const float* __restrict__ queries, const float* __restrict__ values,
        const float* __restrict__ Wi, const float* __restrict__ bi,
        const float* __restrict__ Wm, const float* __restrict__ bm,
        const float* __restrict__ Wq, const float* __restrict__ bq,
        const float* __restrict__ Wk, const float* __restrict__ bk,
        const float* __restrict__ Wv, const float* __restrict__ bv,
        const float* __restrict__ Wo, const float* __restrict__ bo,
        const float* __restrict__ Wx, const float* __restrict__ bl,
        float* __restrict__ out, float m) {
    const int bid = blockIdx.x;
    const int t = threadIdx.x;

    __shared__ __align__(16) float Wg[8][3][64];   // phase-C gate weights
    __shared__ float Bv[8][3];
    __shared__ float x[32];
    __shared__ float aug0[64];
    __shared__ float q[128], k0[128], v0[128];
    __shared__ float logit[130];
    __shared__ float attn[130];
    __shared__ float ctx[128];
    __shared__ float opart[256];
    __shared__ __align__(16) float4 cs4[256];      // colsum partials
    __shared__ float augl[64];
    __shared__ float Hs[8][132];

    const int j0 = bid * 8;
    const int grpoff[3] = {0, 2368, 3552};         // zi, zg, zo column groups

    // ---- Phase A0: prefetch phase-C Wx tile into shared (latency hidden by A/B)
    #pragma unroll
    for (int r = 0; r < 6; r++) {
        int idx = r * NTHR + t;                    // 1536 elements
        int jj = idx & 7;
        int kg = idx >> 3;
        int g  = kg % 3;
        int k  = kg / 3;
        Wg[jj][g][k] = Wx[k * ZDIM + grpoff[g] + j0 + jj];
    }
    if (t < 24) Bv[t & 7][t >> 3] = bl[grpoff[t >> 3] + j0 + (t & 7)];

    // ---- Phase A1: input vector
    if (t < 16)       x[t] = queries[bid * 16 + t];
    else if (t < 32)  x[t] = values[(bid / 16) * 128 + 112 + (t - 16)];
    __syncthreads();

    // ---- Phase A2: emb_in + PE[0]
    if (t < 64) {
        float s = bi[t];
        #pragma unroll
        for (int i = 0; i < 32; i++) s += x[i] * Wi[i * 64 + t];
        aug0[t] = s + ((t & 1) ? 1.0f : 0.0f);
    }
    __syncthreads();

    // ---- Phase A3: q, k0, v0 (threads 0..127, t = h*64+kk)
    if (t < 128) {
        float aq = bq[t], ak = bk[t], av = bv[t];
        #pragma unroll
        for (int d = 0; d < 64; d++) {
            float a = aug0[d];
            aq += a * Wq[d * 128 + t];
            ak += a * Wk[d * 128 + t];
            av += a * Wv[d * 128 + t];
        }
        q[t] = aq; k0[t] = ak; v0[t] = av;
    }

    // ---- Phase A4 (blocks 0..63): colsum(Wm) via independent float4 loads
    if (bid < 64) {
        const float4* wm4 = (const float4*)Wm;     // 4096 float4, col4 = idx & 15
        float4 acc = make_float4(0.f, 0.f, 0.f, 0.f);
        #pragma unroll
        for (int r = 0; r < 16; r++) {
            float4 v = wm4[r * NTHR + t];
            acc.x += v.x; acc.y += v.y; acc.z += v.z; acc.w += v.w;
        }
        cs4[t] = acc;
    }
    __syncthreads();

    if (bid < 64) {
        int l = bid + 1;
        if (t < 64) {
            // column t: contributors cs4[(t>>2) + 16*r], component t&3
            float cs = 0.f;
            const float* base = (const float*)&cs4[t >> 2] + (t & 3);
            #pragma unroll
            for (int r = 0; r < 16; r++) cs += base[r * 64];   // 16 floats stride 16 float4
            augl[t] = m * cs + bm[t] + pe_val(l, t);
        }
        __syncthreads();
        // KC / VC row l: threads 0..127 -> K, 128..255 -> V
        {
            int tt = t & 127, half = t >> 7;
            const float* W  = half ? Wv : Wk;
            const float* bb = half ? bv : bk;
            float* dst      = half ? g_VC : g_KC;
            float a = bb[tt];
            #pragma unroll
            for (int d = 0; d < 64; d++) a += augl[d] * W[d * 128 + tt];
            dst[(l - 1) * 128 + tt] = a;
        }
    }

    grid_bar(&g_bar1);   // KC/VC published

    // ---- Phase B1: logits (2 heads x 65)
    if (t < 130) {
        int h = (t >= 65) ? 1 : 0;
        int l = t - 65 * h;
        const float* kp = (l == 0) ? &k0[h * 64] : &g_KC[(l - 1) * 128 + h * 64];
        float s = 0.0f;
        #pragma unroll
        for (int d = 0; d < 64; d++) s += q[h * 64 + d] * kp[d];
        logit[t] = s * 0.125f;
    }
    __syncthreads();

    // ---- Phase B2: softmax (warp 0 -> head 0, warp 1 -> head 1)
    {
        int w = t >> 5, lane = t & 31;
        if (w < 2) {
            int base = w * 65;
            float a0 = logit[base + lane];
            float a1 = logit[base + 32 + lane];
            float a2 = (lane == 0) ? logit[base + 64] : -1e30f;
            float mx = fmaxf(fmaxf(a0, a1), a2);
            #pragma unroll
            for (int off = 16; off > 0; off >>= 1)
                mx = fmaxf(mx, __shfl_xor_sync(0xffffffffu, mx, off));
            float e0 = __expf(a0 - mx);
            float e1 = __expf(a1 - mx);
            float e2 = (lane == 0) ? __expf(a2 - mx) : 0.0f;
            float sum = e0 + e1 + e2;
            #pragma unroll
            for (int off = 16; off > 0; off >>= 1)
                sum += __shfl_xor_sync(0xffffffffu, sum, off);
            float inv = 1.0f / sum;
            attn[base + lane] = e0 * inv;
            attn[base + 32 + lane] = e1 * inv;
            if (lane == 0) attn[base + 64] = e2 * inv;
        }
    }
    __syncthreads();

    // ---- Phase B3: ctx
    if (t < 128) {
        int h = t >> 6;
        float s = attn[h * 65] * v0[t];
        #pragma unroll
        for (int l = 1; l < 65; l++) s += attn[h * 65 + l] * g_VC[(l - 1) * 128 + t];
        ctx[t] = s;
    }
    __syncthreads();

    // ---- Phase B4: o matvec, 4-way split over hk
    {
        int col = t & 63, qtr = t >> 6;
        float s = qtr ? 0.0f : bo[col];
        const float* Wp = Wo + (qtr * 32) * 64 + col;
        #pragma unroll
        for (int hk = 0; hk < 32; hk++)
            s += ctx[qtr * 32 + hk] * Wp[hk * 64];
        opart[t] = s;
    }
    __syncthreads();
    if (t < 64) g_oT[t * 128 + bid] = opart[t] + opart[t + 64] + opart[t + 128] + opart[t + 192];

    grid_bar(&g_bar2);   // oT published

    // ---- Phase C: gate GEMM from preloaded shared W. thread = (b, jhalf)
    {
        int b = t & 127, jsel = t >> 7;            // jsel 0 -> jj 0..3, 1 -> jj 4..7
        float o[64];
        #pragma unroll
        for (int k = 0; k < 64; k++) o[k] = g_oT[k * 128 + b];

        #pragma unroll
        for (int jr = 0; jr < 4; jr++) {
            int jj = jsel * 4 + jr;
            float zi = Bv[jj][0], zg = Bv[jj][1], zo = Bv[jj][2];
            const float4* wi4 = (const float4*)Wg[jj][0];
            const float4* wg4 = (const float4*)Wg[jj][1];
            const float4* wo4 = (const float4*)Wg[jj][2];
            #pragma unroll
            for (int k4 = 0; k4 < 16; k4++) {
                float4 wi = wi4[k4], wg = wg4[k4], wo = wo4[k4];
                float o0 = o[4 * k4], o1 = o[4 * k4 + 1], o2 = o[4 * k4 + 2], o3 = o[4 * k4 + 3];
                zi += o0 * wi.x + o1 * wi.y + o2 * wi.z + o3 * wi.w;
                zg += o0 * wg.x + o1 * wg.y + o2 * wg.z + o3 * wg.w;
                zo += o0 * wo.x + o1 * wo.y + o2 * wo.z + o3 * wo.w;
            }
            float c = sigd(zi) * tanhf(zg);
            Hs[jj][b] = sigd(zo) * tanhf(c);
        }
    }
    __syncthreads();

    // staged coalesced writes
    #pragma unroll
    for (int r = 0; r < 4; r++) {
        int idx = r * NTHR + t;
        int jj = idx & 7, bb = idx >> 3;
        out[bb * 1024 + j0 + jj] = Hs[jj][bb];
    }

    // ---- Cleanup: last block out resets barrier counters for the next replay
    __syncthreads();
    if (t == 0) {
        __threadfence();
        unsigned d = atomicAdd(&g_done, 1u);
        if (d == (unsigned)(NBLK - 1)) {
            g_bar1 = 0; g_bar2 = 0;
            __threadfence();
            g_done = 0;
        }
    }
}

// ---------------------------------------------------------------------------
// Host-side replica of the pot decay (input-independent).
static float sig_h(float x) { return 1.0f / (1.0f + expf(-x)); }
static float decay_h(float pc, float po) {
    float t0 = 0.07915332f * sig_h(100.0f * (0.0f - 0.5f)) * (1.5931877f - pc);
    float t1 = 1.0334609f  * sig_h(100.0f * (pc - 0.07879465f)) * (1.4378392f - pc);
    float t2 = 1.3365093f  * sig_h(100.0f * (po - 0.06618887f)) * (0.0f - pc);
    float t3 = 0.4505964f  * (0.0f - pc);
    return t0 + t1 + t2 + t3;
}
static float pot_scalar_h() {
    float p0 = 0.0f, p1 = 1.0f;
    const float PART = (float)(1.5573331 / 2.0);
    for (int s = 0; s < 7; s++)
        for (int d = 0; d < 2; d++) {
            float n0 = decay_h(p0, p1);
            float n1 = decay_h(p1, p0);
            p0 += n0 * PART;
            p1 += n1 * PART;
        }
    return p0;
}

extern "C" void kernel_launch(void* const* d_in, const int* in_sizes, int n_in,
                              void* d_out, int out_size) {
    const float* queries = (const float*)d_in[0];
    const float* values  = (const float*)d_in[1];
    const float* Wi      = (const float*)d_in[2];
    const float* bi      = (const float*)d_in[3];
    const float* Wm      = (const float*)d_in[4];
    const float* bm      = (const float*)d_in[5];
    const float* Wq      = (const float*)d_in[6];
    const float* bq      = (const float*)d_in[7];
    const float* Wk      = (const float*)d_in[8];
    const float* bk      = (const float*)d_in[9];
    const float* Wv      = (const float*)d_in[10];
    const float* bv      = (const float*)d_in[11];
    const float* Wo      = (const float*)d_in[12];
    const float* bo      = (const float*)d_in[13];
    const float* Wx      = (const float*)d_in[14];
    const float* bl      = (const float*)d_in[15];
    float* out = (float*)d_out;

    float m = pot_scalar_h();

    k_fused<<<NBLK, NTHR>>>(queries, values, Wi, bi, Wm, bm, Wq, bq, Wk, bk,
                            Wv, bv, Wo, bo, Wx, bl, out, m);
}